// round 16
// baseline (speedup 1.0000x reference)
#include <cuda_runtime.h>
#include <cuda_fp16.h>
#include <math.h>
#include <stdint.h>

#define DIM    3072
#define NHEADS 24
#define HDIM   128
#define SEQ    2304

// ---------------------------------------------------------------------------
// Scratch (allocation-free: __device__ globals)
// ---------------------------------------------------------------------------
__device__ float g_q[SEQ * DIM];
__device__ float g_k[SEQ * DIM];
__device__ float g_dummy[SEQ * DIM];

__device__ __half g_xs[SEQ * DIM];                      // x single fp16
__device__ __half g_as[SEQ * DIM];                      // attn single fp16
__device__ __half g_wq[DIM * DIM], g_wk[DIM * DIM];     // weights single fp16
__device__ __half g_wv[DIM * DIM], g_wo[DIM * DIM];
__device__ __half g_qs[SEQ * DIM];                      // Q single fp16
__device__ __half g_ks[SEQ * DIM];                      // K single fp16
__device__ __half g_vs[SEQ * DIM];                      // V single fp16 (GEMM-written)

__device__ __forceinline__ uint32_t pack2h(float a, float b) {
    __half2 h = __floats2half2_rn(a, b);
    return *reinterpret_cast<uint32_t*>(&h);
}

__device__ __forceinline__ void cp16(uint32_t saddr, const void* gptr) {
    asm volatile("cp.async.cg.shared.global [%0], [%1], 16;"
                 :: "r"(saddr), "l"(gptr));
}

#define MMA_F16(d, a, b)                                                      \
    asm volatile("mma.sync.aligned.m16n8k16.row.col.f32.f16.f16.f32 "         \
                 "{%0,%1,%2,%3}, {%4,%5,%6,%7}, {%8,%9}, {%0,%1,%2,%3};"      \
                 : "+f"(d[0]), "+f"(d[1]), "+f"(d[2]), "+f"(d[3])             \
                 : "r"(a[0]), "r"(a[1]), "r"(a[2]), "r"(a[3]),                \
                   "r"(b[0]), "r"(b[1]))

// ---------------------------------------------------------------------------
// Fused fp32 -> fp16 conversion over 5 regions (x, wq, wk, wv, wo).
// ---------------------------------------------------------------------------
struct ConvBatch {
    const float* src[5];
    __half*      dst[5];
    int          off[6];   // cumulative offsets in float4 units
};

__global__ __launch_bounds__(256)
void round_f16_multi(ConvBatch cb, int total4) {
    const int i = blockIdx.x * 256 + threadIdx.x;
    if (i >= total4) return;
    int r = 0;
#pragma unroll
    for (int j = 1; j < 5; j++) if (i >= cb.off[j]) r = j;
    const int e = (i - cb.off[r]) * 4;
    float4 v = *(const float4*)(cb.src[r] + e);
    *(uint2*)(cb.dst[r] + e) = make_uint2(pack2h(v.x, v.y), pack2h(v.z, v.w));
}

// ---------------------------------------------------------------------------
// Single-pass fp16 GEMM (NT): C = A . B^T + bias, fp32 accum. (R14, passing)
// ---------------------------------------------------------------------------
#define SSTR 20
#define ARR_U32 (128 * SSTR)
#define ARR_BYTES (ARR_U32 * 4)
#define STG_U32 (2 * ARR_U32)
#define STG_BYTES (STG_U32 * 4)

struct GemmF16Batch {
    const __half* B[3];
    const float*  bias[3];
    float*        C[3];
    __half*       Ch[3];
};

__global__ __launch_bounds__(256, 2)
void gemm_f16_pipe(const __half* __restrict__ A,
                   GemmF16Batch batch, int M, int N, int K) {
    extern __shared__ uint32_t smem[];
    const uint32_t sbase = (uint32_t)__cvta_generic_to_shared(smem);

    const __half* __restrict__ B = batch.B[blockIdx.z];
    const float* __restrict__ bias = batch.bias[blockIdx.z];
    float* __restrict__ C = batch.C[blockIdx.z];
    __half* __restrict__ Ch = batch.Ch[blockIdx.z];

    const int bm = blockIdx.y * 128, bn = blockIdx.x * 128;
    const int tid = threadIdx.x;
    const int w = tid >> 5, lane = tid & 31;
    const int wm = w & 1, wn = w >> 1;
    const int g = lane >> 2, tg = lane & 3;

    float acc[4][4][4];
#pragma unroll
    for (int mi = 0; mi < 4; mi++)
#pragma unroll
        for (int ni = 0; ni < 4; ni++)
#pragma unroll
            for (int r = 0; r < 4; r++) acc[mi][ni][r] = 0.f;

    auto issue = [&](int kt, int stage) {
        const uint32_t sb = sbase + (uint32_t)stage * STG_BYTES;
#pragma unroll
        for (int i = 0; i < 4; i++) {
            const int c = tid + i * 256;
            const int arr = c >> 9;
            const int cid = c & 511;
            const int r = cid >> 2, q = cid & 3;
            const uint32_t dst = sb + arr * ARR_BYTES + (r * SSTR + q * 4) * 4;
            const __half* src = (arr == 0)
                ? A + (size_t)(bm + r) * K + kt + q * 8
                : B + (size_t)(bn + r) * K + kt + q * 8;
            cp16(dst, src);
        }
    };

    const int ntiles = K / 32;
    issue(0, 0);
    asm volatile("cp.async.commit_group;");

    for (int t = 0; t < ntiles; t++) {
        if (t + 1 < ntiles) issue((t + 1) * 32, (t + 1) & 1);
        asm volatile("cp.async.commit_group;");
        asm volatile("cp.async.wait_group 1;");
        __syncthreads();

        const uint32_t* sA = smem + (t & 1) * STG_U32;
        const uint32_t* sB = sA + ARR_U32;

#pragma unroll
        for (int ks = 0; ks < 2; ks++) {
            const int kb = ks * 8;
            uint32_t af[4][4], bf[4][2];
#pragma unroll
            for (int mi = 0; mi < 4; mi++) {
                const int r = wm * 64 + mi * 16 + g;
                af[mi][0] = sA[r * SSTR + kb + tg];
                af[mi][1] = sA[(r + 8) * SSTR + kb + tg];
                af[mi][2] = sA[r * SSTR + kb + tg + 4];
                af[mi][3] = sA[(r + 8) * SSTR + kb + tg + 4];
            }
#pragma unroll
            for (int ni = 0; ni < 4; ni++) {
                const int c = wn * 32 + ni * 8 + g;
                bf[ni][0] = sB[c * SSTR + kb + tg];
                bf[ni][1] = sB[c * SSTR + kb + tg + 4];
            }
#pragma unroll
            for (int mi = 0; mi < 4; mi++)
#pragma unroll
                for (int ni = 0; ni < 4; ni++)
                    MMA_F16(acc[mi][ni], af[mi], bf[ni]);
        }
        __syncthreads();
    }

#pragma unroll
    for (int mi = 0; mi < 4; mi++)
#pragma unroll
        for (int ni = 0; ni < 4; ni++) {
            const int r = bm + wm * 64 + mi * 16 + g;
            const int c = bn + wn * 32 + ni * 8 + tg * 2;
            const float b0 = bias[c], b1 = bias[c + 1];
            if (Ch) {
                uint32_t* dst = (uint32_t*)Ch;
                dst[((size_t)r * N + c) >> 1] =
                    pack2h(acc[mi][ni][0] + b0, acc[mi][ni][1] + b1);
                dst[((size_t)(r + 8) * N + c) >> 1] =
                    pack2h(acc[mi][ni][2] + b0, acc[mi][ni][3] + b1);
            } else {
                C[(size_t)r * N + c]           = acc[mi][ni][0] + b0;
                C[(size_t)r * N + c + 1]       = acc[mi][ni][1] + b1;
                C[(size_t)(r + 8) * N + c]     = acc[mi][ni][2] + b0;
                C[(size_t)(r + 8) * N + c + 1] = acc[mi][ni][3] + b1;
            }
        }
}

// ---------------------------------------------------------------------------
// Fused fp32 RMSNorm + 3-axis RoPE + scale -> single fp16.
// blockIdx.y selects (buf, g, out, scale)  [0 = q, 1 = k].
// ---------------------------------------------------------------------------
struct NormBatch {
    const float* buf[2];
    const float* g[2];
    __half*      out[2];
    float        scale[2];
};

__global__ __launch_bounds__(256)
void norm_rope_pack2(NormBatch nb, const float* __restrict__ freqs,
                     const int* __restrict__ grid_sizes) {
    __shared__ float red[256];
    __shared__ float s_rn;
    const int z = blockIdx.y;
    const float* __restrict__ buf = nb.buf[z];
    const float* __restrict__ g   = nb.g[z];
    __half* __restrict__ o        = nb.out[z];
    const float scale             = nb.scale[z];

    const int row = blockIdx.x;
    const int tid = threadIdx.x;
    const float* rp = buf + (size_t)row * DIM;

    float ss = 0.f;
    for (int i = tid; i < DIM; i += 256) { float v = rp[i]; ss += v * v; }
    red[tid] = ss;
    __syncthreads();
#pragma unroll
    for (int st = 128; st > 0; st >>= 1) {
        if (tid < st) red[tid] += red[tid + st];
        __syncthreads();
    }
    if (tid == 0) s_rn = rsqrtf(red[0] / (float)DIM + 1e-6f);
    __syncthreads();
    const float rn = s_rn;

    const int gh = grid_sizes[1];
    const int gw = grid_sizes[2];
    const int fi = row / (gh * gw);
    const int hi = (row % (gh * gw)) / gw;
    const int wi = row % gw;

    for (int p = tid; p < DIM / 2; p += 256) {
        const int c = p & 63;
        const int pos = (c < 22) ? fi : ((c < 43) ? hi : wi);
        const float theta = freqs[pos * 64 + c];
        float sn, cs;
        sincosf(theta, &sn, &cs);
        const int idx = (p >> 6) * HDIM + 2 * c;
        const float xr = rp[idx]     * rn * g[idx];
        const float xi = rp[idx + 1] * rn * g[idx + 1];
        const float y0 = (xr * cs - xi * sn) * scale;
        const float y1 = (xr * sn + xi * cs) * scale;
        *(uint32_t*)(o + (size_t)row * DIM + idx) = pack2h(y0, y1);
    }
}

// ---------------------------------------------------------------------------
// Tensor-core flash attention — R14 version VERBATIM (single-stage K/V,
// cp.async, row-major V + ldmatrix.x2.trans, occupancy 3).
// ---------------------------------------------------------------------------
#define FSTR 68   // u32 stride for Q/K/V smem rows (64 data + 4 pad)

__global__ __launch_bounds__(128, 3)
void flash_f16s(const __half* __restrict__ Q, const __half* __restrict__ K,
                const __half* __restrict__ V, const int* __restrict__ seq_lens,
                __half* __restrict__ O) {
    extern __shared__ uint32_t sm[];
    uint32_t* sQ = sm;
    uint32_t* sK = sQ + 64 * FSTR;

    const uint32_t smb = (uint32_t)__cvta_generic_to_shared(sm);
    const uint32_t bK = smb + 64 * FSTR * 4;
    const uint32_t bV = bK + 64 * FSTR * 4;

    const int head = blockIdx.y;
    const int q0 = blockIdx.x * 64;
    const int tid = threadIdx.x;
    const int w = tid >> 5, lane = tid & 31;
    const int g = lane >> 2, tg = lane & 3;
    const int m0 = w * 16;
    const int seqlen = seq_lens[0];
    const int GROW = DIM / 2;

    // ---- load Q tile (scalar, once) ----
    {
        const uint32_t* gQ = (const uint32_t*)(Q + (size_t)q0 * DIM + head * HDIM);
        for (int i = tid; i < 64 * 64; i += 128) {
            const int r = i >> 6, c = i & 63;
            sQ[r * FSTR + c] = gQ[(size_t)r * GROW + c];
        }
    }

    float m[2] = {-1e30f, -1e30f}, l[2] = {0.f, 0.f};
    float o[16][4];
#pragma unroll
    for (int n = 0; n < 16; n++)
#pragma unroll
        for (int r = 0; r < 4; r++) o[n][r] = 0.f;

    for (int k0 = 0; k0 < SEQ; k0 += 64) {
        if (k0 >= seqlen) break;
        __syncthreads();   // prior tile's compute done before overwrite

        // ---- cp.async K and V tiles (row-major) ----
        {
            const __half* gK = K + (size_t)k0 * DIM + head * HDIM;
            const __half* gV = V + (size_t)k0 * DIM + head * HDIM;
#pragma unroll
            for (int i = 0; i < 8; i++) {
                const int c = tid + i * 128;
                const int r = c >> 4, q = c & 15;
                cp16(bK + (r * FSTR + q * 4) * 4, gK + (size_t)r * DIM + q * 8);
                cp16(bV + (r * FSTR + q * 4) * 4, gV + (size_t)r * DIM + q * 8);
            }
        }
        asm volatile("cp.async.commit_group;");
        asm volatile("cp.async.wait_group 0;");
        __syncthreads();

        // ---- scores S = Q K^T (single pass) ----
        float s[8][4];
#pragma unroll
        for (int j = 0; j < 8; j++)
#pragma unroll
            for (int r = 0; r < 4; r++) s[j][r] = 0.f;

#pragma unroll
        for (int ks = 0; ks < 8; ks++) {
            uint32_t aq[4];
            const int ab = (m0 + g) * FSTR + ks * 8 + tg;
            aq[0] = sQ[ab];            aq[1] = sQ[ab + 8 * FSTR];
            aq[2] = sQ[ab + 4];        aq[3] = sQ[ab + 8 * FSTR + 4];
#pragma unroll
            for (int j = 0; j < 8; j++) {
                uint32_t bf[2];
                const int kb = (8 * j + g) * FSTR + ks * 8 + tg;
                bf[0] = sK[kb]; bf[1] = sK[kb + 4];
                MMA_F16(s[j], aq, bf);
            }
        }

        // ---- online softmax ----
        const int kv = seqlen - k0;
        float mx0 = -1e30f, mx1 = -1e30f;
#pragma unroll
        for (int j = 0; j < 8; j++) {
            const int c0 = 8 * j + 2 * tg, c1 = c0 + 1;
            if (c0 >= kv) { s[j][0] = -1e30f; s[j][2] = -1e30f; }
            if (c1 >= kv) { s[j][1] = -1e30f; s[j][3] = -1e30f; }
            mx0 = fmaxf(mx0, fmaxf(s[j][0], s[j][1]));
            mx1 = fmaxf(mx1, fmaxf(s[j][2], s[j][3]));
        }
        mx0 = fmaxf(mx0, __shfl_xor_sync(0xffffffff, mx0, 1));
        mx0 = fmaxf(mx0, __shfl_xor_sync(0xffffffff, mx0, 2));
        mx1 = fmaxf(mx1, __shfl_xor_sync(0xffffffff, mx1, 1));
        mx1 = fmaxf(mx1, __shfl_xor_sync(0xffffffff, mx1, 2));
        const float mn0 = fmaxf(m[0], mx0);
        const float mn1 = fmaxf(m[1], mx1);
        const float a0 = __expf(m[0] - mn0);
        const float a1 = __expf(m[1] - mn1);
        m[0] = mn0; m[1] = mn1;

        float sum0 = 0.f, sum1 = 0.f;
#pragma unroll
        for (int j = 0; j < 8; j++) {
            s[j][0] = __expf(s[j][0] - mn0);
            s[j][1] = __expf(s[j][1] - mn0);
            s[j][2] = __expf(s[j][2] - mn1);
            s[j][3] = __expf(s[j][3] - mn1);
            sum0 += s[j][0] + s[j][1];
            sum1 += s[j][2] + s[j][3];
        }
        sum0 += __shfl_xor_sync(0xffffffff, sum0, 1);
        sum0 += __shfl_xor_sync(0xffffffff, sum0, 2);
        sum1 += __shfl_xor_sync(0xffffffff, sum1, 1);
        sum1 += __shfl_xor_sync(0xffffffff, sum1, 2);
        l[0] = l[0] * a0 + sum0;
        l[1] = l[1] * a1 + sum1;

#pragma unroll
        for (int n = 0; n < 16; n++) {
            o[n][0] *= a0; o[n][1] *= a0;
            o[n][2] *= a1; o[n][3] *= a1;
        }

        // ---- O += P V  (ldmatrix.x2.trans on row-major V) ----
#pragma unroll
        for (int kp = 0; kp < 4; kp++) {
            uint32_t ph[4];
            const int j0 = 2 * kp, j1 = 2 * kp + 1;
            ph[0] = pack2h(s[j0][0], s[j0][1]);
            ph[1] = pack2h(s[j0][2], s[j0][3]);
            ph[2] = pack2h(s[j1][0], s[j1][1]);
            ph[3] = pack2h(s[j1][2], s[j1][3]);
            const uint32_t vrow = bV + (uint32_t)(kp * 16 + (lane & 15)) * (FSTR * 4);
#pragma unroll
            for (int n2 = 0; n2 < 16; n2++) {
                uint32_t bv[2];
                asm volatile(
                    "ldmatrix.sync.aligned.m8n8.x2.trans.shared.b16 {%0,%1}, [%2];"
                    : "=r"(bv[0]), "=r"(bv[1])
                    : "r"(vrow + n2 * 16));
                MMA_F16(o[n2], ph, bv);
            }
        }
    }

    // ---- epilogue: normalize, write single fp16 ----
    const float inv0 = 1.f / l[0];
    const float inv1 = 1.f / l[1];
    const int r0 = q0 + m0 + g;
    const int r1 = r0 + 8;
    uint32_t* oO = (uint32_t*)(O);
#pragma unroll
    for (int n = 0; n < 16; n++) {
        const int col = head * HDIM + 8 * n + 2 * tg;
        oO[(size_t)r0 * GROW + col / 2] = pack2h(o[n][0] * inv0, o[n][1] * inv0);
        oO[(size_t)r1 * GROW + col / 2] = pack2h(o[n][2] * inv1, o[n][3] * inv1);
    }
}

// ---------------------------------------------------------------------------
// Launch
// ---------------------------------------------------------------------------
extern "C" void kernel_launch(void* const* d_in, const int* in_sizes, int n_in,
                              void* d_out, int out_size) {
    const float* x         = (const float*)d_in[0];
    const int*   seq_lens  = (const int*)  d_in[1];
    const int*   grid_sz   = (const int*)  d_in[2];
    const float* freqs     = (const float*)d_in[3];
    const float* wq        = (const float*)d_in[4];
    const float* bq        = (const float*)d_in[5];
    const float* wk        = (const float*)d_in[6];
    const float* bk        = (const float*)d_in[7];
    const float* wv        = (const float*)d_in[8];
    const float* bv        = (const float*)d_in[9];
    const float* wo        = (const float*)d_in[10];
    const float* bo        = (const float*)d_in[11];
    const float* gq        = (const float*)d_in[12];
    const float* gk        = (const float*)d_in[13];
    float* out = (float*)d_out;

    float *q, *k, *dummy;
    cudaGetSymbolAddress((void**)&q, g_q);
    cudaGetSymbolAddress((void**)&k, g_k);
    cudaGetSymbolAddress((void**)&dummy, g_dummy);

    __half *xs, *as, *hwq, *hwk, *hwv, *hwo, *qs, *ks, *vs;
    cudaGetSymbolAddress((void**)&xs,  g_xs); cudaGetSymbolAddress((void**)&as,  g_as);
    cudaGetSymbolAddress((void**)&hwq, g_wq); cudaGetSymbolAddress((void**)&hwk, g_wk);
    cudaGetSymbolAddress((void**)&hwv, g_wv); cudaGetSymbolAddress((void**)&hwo, g_wo);
    cudaGetSymbolAddress((void**)&qs,  g_qs); cudaGetSymbolAddress((void**)&ks,  g_ks);
    cudaGetSymbolAddress((void**)&vs,  g_vs);

    const int nX = SEQ * DIM, nW = DIM * DIM;
    const int gemm_smem = 2 * STG_BYTES;   // 40960 bytes
    cudaFuncSetAttribute(gemm_f16_pipe,
                         cudaFuncAttributeMaxDynamicSharedMemorySize, gemm_smem);

    // launch 1: all fp32->fp16 conversions fused
    ConvBatch cb;
    cb.src[0] = x;  cb.dst[0] = xs;
    cb.src[1] = wq; cb.dst[1] = hwq;
    cb.src[2] = wk; cb.dst[2] = hwk;
    cb.src[3] = wv; cb.dst[3] = hwv;
    cb.src[4] = wo; cb.dst[4] = hwo;
    cb.off[0] = 0;
    cb.off[1] = nX / 4;
    cb.off[2] = cb.off[1] + nW / 4;
    cb.off[3] = cb.off[2] + nW / 4;
    cb.off[4] = cb.off[3] + nW / 4;
    cb.off[5] = cb.off[4] + nW / 4;
    round_f16_multi<<<(cb.off[5] + 255) / 256, 256>>>(cb, cb.off[5]);

    // launch 2: fused QKV GEMM; V written directly as fp16
    GemmF16Batch qkv;
    qkv.B[0] = hwq; qkv.bias[0] = bq; qkv.C[0] = q;     qkv.Ch[0] = nullptr;
    qkv.B[1] = hwk; qkv.bias[1] = bk; qkv.C[1] = k;     qkv.Ch[1] = nullptr;
    qkv.B[2] = hwv; qkv.bias[2] = bv; qkv.C[2] = dummy; qkv.Ch[2] = vs;
    gemm_f16_pipe<<<dim3(DIM / 128, SEQ / 128, 3), 256, gemm_smem>>>(
        xs, qkv, SEQ, DIM, DIM);

    // launch 3: fused q+k norm/rope
    const float scale = 0.08838834764831845f;   // 1/sqrt(128)
    NormBatch nb;
    nb.buf[0] = q;  nb.g[0] = gq; nb.out[0] = qs; nb.scale[0] = scale;
    nb.buf[1] = k;  nb.g[1] = gk; nb.out[1] = ks; nb.scale[1] = 1.0f;
    norm_rope_pack2<<<dim3(SEQ, 2), 256>>>(nb, freqs, grid_sz);

    // launch 4: flash attention (R14 single-stage, occupancy 3)
    const size_t fl_smem = (size_t)(3 * 64 * FSTR) * sizeof(uint32_t);  // 52224
    cudaFuncSetAttribute(flash_f16s, cudaFuncAttributeMaxDynamicSharedMemorySize,
                         (int)fl_smem);
    flash_f16s<<<dim3(SEQ / 64, NHEADS), 128, fl_smem>>>(qs, ks, vs, seq_lens, as);

    // launch 5: O-projection GEMM
    GemmF16Batch ob;
    ob.B[0] = hwo; ob.bias[0] = bo; ob.C[0] = out; ob.Ch[0] = nullptr;
    ob.B[1] = hwo; ob.bias[1] = bo; ob.C[1] = out; ob.Ch[1] = nullptr;
    ob.B[2] = hwo; ob.bias[2] = bo; ob.C[2] = out; ob.Ch[2] = nullptr;
    gemm_f16_pipe<<<dim3(DIM / 128, SEQ / 128, 1), 256, gemm_smem>>>(
        as, ob, SEQ, DIM, DIM);
}

// round 17
// speedup vs baseline: 1.1068x; 1.1068x over previous
#include <cuda_runtime.h>
#include <cuda_fp16.h>
#include <math.h>
#include <stdint.h>

#define DIM    3072
#define NHEADS 24
#define HDIM   128
#define SEQ    2304

// ---------------------------------------------------------------------------
// Scratch (allocation-free: __device__ globals)
// ---------------------------------------------------------------------------
__device__ float g_q[SEQ * DIM];
__device__ float g_k[SEQ * DIM];
__device__ float g_dummy[SEQ * DIM];

__device__ __half g_xs[SEQ * DIM];                      // x single fp16
__device__ __half g_as[SEQ * DIM];                      // attn single fp16
__device__ __half g_wq[DIM * DIM], g_wk[DIM * DIM];     // weights single fp16
__device__ __half g_wv[DIM * DIM], g_wo[DIM * DIM];
__device__ __half g_qs[SEQ * DIM];                      // Q single fp16
__device__ __half g_ks[SEQ * DIM];                      // K single fp16
__device__ __half g_vs[SEQ * DIM];                      // V single fp16 (GEMM-written)

__device__ __forceinline__ uint32_t pack2h(float a, float b) {
    __half2 h = __floats2half2_rn(a, b);
    return *reinterpret_cast<uint32_t*>(&h);
}

__device__ __forceinline__ void cp16(uint32_t saddr, const void* gptr) {
    asm volatile("cp.async.cg.shared.global [%0], [%1], 16;"
                 :: "r"(saddr), "l"(gptr));
}

#define MMA_F16(d, a, b)                                                      \
    asm volatile("mma.sync.aligned.m16n8k16.row.col.f32.f16.f16.f32 "         \
                 "{%0,%1,%2,%3}, {%4,%5,%6,%7}, {%8,%9}, {%0,%1,%2,%3};"      \
                 : "+f"(d[0]), "+f"(d[1]), "+f"(d[2]), "+f"(d[3])             \
                 : "r"(a[0]), "r"(a[1]), "r"(a[2]), "r"(a[3]),                \
                   "r"(b[0]), "r"(b[1]))

// ---------------------------------------------------------------------------
// Fused fp32 -> fp16 conversion, COMPILE-TIME region bounds, named params
// (no dynamic indexing of kernel parameters -> no local-memory demotion).
// ---------------------------------------------------------------------------
#define NX4 ((SEQ * DIM) / 4)
#define NW4 ((DIM * DIM) / 4)

__global__ __launch_bounds__(256)
void conv_all(const float* __restrict__ x,  const float* __restrict__ wq,
              const float* __restrict__ wk, const float* __restrict__ wv,
              const float* __restrict__ wo,
              __half* __restrict__ xs,  __half* __restrict__ hwq,
              __half* __restrict__ hwk, __half* __restrict__ hwv,
              __half* __restrict__ hwo) {
    const int i = blockIdx.x * 256 + threadIdx.x;
    const float* src;
    __half* dst;
    int e;
    if (i < NX4)                    { src = x;  dst = xs;  e = i; }
    else if (i < NX4 + NW4)         { src = wq; dst = hwq; e = i - NX4; }
    else if (i < NX4 + 2 * NW4)     { src = wk; dst = hwk; e = i - NX4 - NW4; }
    else if (i < NX4 + 3 * NW4)     { src = wv; dst = hwv; e = i - NX4 - 2 * NW4; }
    else if (i < NX4 + 4 * NW4)     { src = wo; dst = hwo; e = i - NX4 - 3 * NW4; }
    else return;
    float4 v = *(const float4*)(src + (size_t)e * 4);
    *(uint2*)(dst + (size_t)e * 4) = make_uint2(pack2h(v.x, v.y), pack2h(v.z, v.w));
}

// ---------------------------------------------------------------------------
// Single-pass fp16 GEMM (NT): C = A . B^T + bias, fp32 accum. (R14, passing)
// ---------------------------------------------------------------------------
#define SSTR 20
#define ARR_U32 (128 * SSTR)
#define ARR_BYTES (ARR_U32 * 4)
#define STG_U32 (2 * ARR_U32)
#define STG_BYTES (STG_U32 * 4)

struct GemmF16Batch {
    const __half* B[3];
    const float*  bias[3];
    float*        C[3];
    __half*       Ch[3];
};

__global__ __launch_bounds__(256, 2)
void gemm_f16_pipe(const __half* __restrict__ A,
                   GemmF16Batch batch, int M, int N, int K) {
    extern __shared__ uint32_t smem[];
    const uint32_t sbase = (uint32_t)__cvta_generic_to_shared(smem);

    const __half* __restrict__ B = batch.B[blockIdx.z];
    const float* __restrict__ bias = batch.bias[blockIdx.z];
    float* __restrict__ C = batch.C[blockIdx.z];
    __half* __restrict__ Ch = batch.Ch[blockIdx.z];

    const int bm = blockIdx.y * 128, bn = blockIdx.x * 128;
    const int tid = threadIdx.x;
    const int w = tid >> 5, lane = tid & 31;
    const int wm = w & 1, wn = w >> 1;
    const int g = lane >> 2, tg = lane & 3;

    float acc[4][4][4];
#pragma unroll
    for (int mi = 0; mi < 4; mi++)
#pragma unroll
        for (int ni = 0; ni < 4; ni++)
#pragma unroll
            for (int r = 0; r < 4; r++) acc[mi][ni][r] = 0.f;

    auto issue = [&](int kt, int stage) {
        const uint32_t sb = sbase + (uint32_t)stage * STG_BYTES;
#pragma unroll
        for (int i = 0; i < 4; i++) {
            const int c = tid + i * 256;
            const int arr = c >> 9;
            const int cid = c & 511;
            const int r = cid >> 2, q = cid & 3;
            const uint32_t dst = sb + arr * ARR_BYTES + (r * SSTR + q * 4) * 4;
            const __half* src = (arr == 0)
                ? A + (size_t)(bm + r) * K + kt + q * 8
                : B + (size_t)(bn + r) * K + kt + q * 8;
            cp16(dst, src);
        }
    };

    const int ntiles = K / 32;
    issue(0, 0);
    asm volatile("cp.async.commit_group;");

    for (int t = 0; t < ntiles; t++) {
        if (t + 1 < ntiles) issue((t + 1) * 32, (t + 1) & 1);
        asm volatile("cp.async.commit_group;");
        asm volatile("cp.async.wait_group 1;");
        __syncthreads();

        const uint32_t* sA = smem + (t & 1) * STG_U32;
        const uint32_t* sB = sA + ARR_U32;

#pragma unroll
        for (int ks = 0; ks < 2; ks++) {
            const int kb = ks * 8;
            uint32_t af[4][4], bf[4][2];
#pragma unroll
            for (int mi = 0; mi < 4; mi++) {
                const int r = wm * 64 + mi * 16 + g;
                af[mi][0] = sA[r * SSTR + kb + tg];
                af[mi][1] = sA[(r + 8) * SSTR + kb + tg];
                af[mi][2] = sA[r * SSTR + kb + tg + 4];
                af[mi][3] = sA[(r + 8) * SSTR + kb + tg + 4];
            }
#pragma unroll
            for (int ni = 0; ni < 4; ni++) {
                const int c = wn * 32 + ni * 8 + g;
                bf[ni][0] = sB[c * SSTR + kb + tg];
                bf[ni][1] = sB[c * SSTR + kb + tg + 4];
            }
#pragma unroll
            for (int mi = 0; mi < 4; mi++)
#pragma unroll
                for (int ni = 0; ni < 4; ni++)
                    MMA_F16(acc[mi][ni], af[mi], bf[ni]);
        }
        __syncthreads();
    }

#pragma unroll
    for (int mi = 0; mi < 4; mi++)
#pragma unroll
        for (int ni = 0; ni < 4; ni++) {
            const int r = bm + wm * 64 + mi * 16 + g;
            const int c = bn + wn * 32 + ni * 8 + tg * 2;
            const float b0 = bias[c], b1 = bias[c + 1];
            if (Ch) {
                uint32_t* dst = (uint32_t*)Ch;
                dst[((size_t)r * N + c) >> 1] =
                    pack2h(acc[mi][ni][0] + b0, acc[mi][ni][1] + b1);
                dst[((size_t)(r + 8) * N + c) >> 1] =
                    pack2h(acc[mi][ni][2] + b0, acc[mi][ni][3] + b1);
            } else {
                C[(size_t)r * N + c]           = acc[mi][ni][0] + b0;
                C[(size_t)r * N + c + 1]       = acc[mi][ni][1] + b1;
                C[(size_t)(r + 8) * N + c]     = acc[mi][ni][2] + b0;
                C[(size_t)(r + 8) * N + c + 1] = acc[mi][ni][3] + b1;
            }
        }
}

// ---------------------------------------------------------------------------
// Fused q+k RMSNorm + RoPE + scale -> fp16. Named params, ternary select
// on blockIdx.y (uniform branch, no local memory).
// ---------------------------------------------------------------------------
__global__ __launch_bounds__(256)
void norm_rope_qk(const float* __restrict__ qbuf, const float* __restrict__ kbuf,
                  const float* __restrict__ gq, const float* __restrict__ gk,
                  __half* __restrict__ qo, __half* __restrict__ ko,
                  const float* __restrict__ freqs,
                  const int* __restrict__ grid_sizes, float qscale) {
    __shared__ float red[256];
    __shared__ float s_rn;
    const bool isq = (blockIdx.y == 0);
    const float* __restrict__ buf = isq ? qbuf : kbuf;
    const float* __restrict__ g   = isq ? gq   : gk;
    __half* __restrict__ o        = isq ? qo   : ko;
    const float scale             = isq ? qscale : 1.0f;

    const int row = blockIdx.x;
    const int tid = threadIdx.x;
    const float* rp = buf + (size_t)row * DIM;

    float ss = 0.f;
    for (int i = tid; i < DIM; i += 256) { float v = rp[i]; ss += v * v; }
    red[tid] = ss;
    __syncthreads();
#pragma unroll
    for (int st = 128; st > 0; st >>= 1) {
        if (tid < st) red[tid] += red[tid + st];
        __syncthreads();
    }
    if (tid == 0) s_rn = rsqrtf(red[0] / (float)DIM + 1e-6f);
    __syncthreads();
    const float rn = s_rn;

    const int gh = grid_sizes[1];
    const int gw = grid_sizes[2];
    const int fi = row / (gh * gw);
    const int hi = (row % (gh * gw)) / gw;
    const int wi = row % gw;

    for (int p = tid; p < DIM / 2; p += 256) {
        const int c = p & 63;
        const int pos = (c < 22) ? fi : ((c < 43) ? hi : wi);
        const float theta = freqs[pos * 64 + c];
        float sn, cs;
        sincosf(theta, &sn, &cs);
        const int idx = (p >> 6) * HDIM + 2 * c;
        const float xr = rp[idx]     * rn * g[idx];
        const float xi = rp[idx + 1] * rn * g[idx + 1];
        const float y0 = (xr * cs - xi * sn) * scale;
        const float y1 = (xr * sn + xi * cs) * scale;
        *(uint32_t*)(o + (size_t)row * DIM + idx) = pack2h(y0, y1);
    }
}

// ---------------------------------------------------------------------------
// Tensor-core flash attention — R14 version VERBATIM (single-stage K/V,
// cp.async, row-major V + ldmatrix.x2.trans, occupancy 3).
// ---------------------------------------------------------------------------
#define FSTR 68   // u32 stride for Q/K/V smem rows (64 data + 4 pad)

__global__ __launch_bounds__(128, 3)
void flash_f16s(const __half* __restrict__ Q, const __half* __restrict__ K,
                const __half* __restrict__ V, const int* __restrict__ seq_lens,
                __half* __restrict__ O) {
    extern __shared__ uint32_t sm[];
    uint32_t* sQ = sm;
    uint32_t* sK = sQ + 64 * FSTR;

    const uint32_t smb = (uint32_t)__cvta_generic_to_shared(sm);
    const uint32_t bK = smb + 64 * FSTR * 4;
    const uint32_t bV = bK + 64 * FSTR * 4;

    const int head = blockIdx.y;
    const int q0 = blockIdx.x * 64;
    const int tid = threadIdx.x;
    const int w = tid >> 5, lane = tid & 31;
    const int g = lane >> 2, tg = lane & 3;
    const int m0 = w * 16;
    const int seqlen = seq_lens[0];
    const int GROW = DIM / 2;

    {
        const uint32_t* gQ = (const uint32_t*)(Q + (size_t)q0 * DIM + head * HDIM);
        for (int i = tid; i < 64 * 64; i += 128) {
            const int r = i >> 6, c = i & 63;
            sQ[r * FSTR + c] = gQ[(size_t)r * GROW + c];
        }
    }

    float m[2] = {-1e30f, -1e30f}, l[2] = {0.f, 0.f};
    float o[16][4];
#pragma unroll
    for (int n = 0; n < 16; n++)
#pragma unroll
        for (int r = 0; r < 4; r++) o[n][r] = 0.f;

    for (int k0 = 0; k0 < SEQ; k0 += 64) {
        if (k0 >= seqlen) break;
        __syncthreads();

        {
            const __half* gK = K + (size_t)k0 * DIM + head * HDIM;
            const __half* gV = V + (size_t)k0 * DIM + head * HDIM;
#pragma unroll
            for (int i = 0; i < 8; i++) {
                const int c = tid + i * 128;
                const int r = c >> 4, q = c & 15;
                cp16(bK + (r * FSTR + q * 4) * 4, gK + (size_t)r * DIM + q * 8);
                cp16(bV + (r * FSTR + q * 4) * 4, gV + (size_t)r * DIM + q * 8);
            }
        }
        asm volatile("cp.async.commit_group;");
        asm volatile("cp.async.wait_group 0;");
        __syncthreads();

        float s[8][4];
#pragma unroll
        for (int j = 0; j < 8; j++)
#pragma unroll
            for (int r = 0; r < 4; r++) s[j][r] = 0.f;

#pragma unroll
        for (int ks = 0; ks < 8; ks++) {
            uint32_t aq[4];
            const int ab = (m0 + g) * FSTR + ks * 8 + tg;
            aq[0] = sQ[ab];            aq[1] = sQ[ab + 8 * FSTR];
            aq[2] = sQ[ab + 4];        aq[3] = sQ[ab + 8 * FSTR + 4];
#pragma unroll
            for (int j = 0; j < 8; j++) {
                uint32_t bf[2];
                const int kb = (8 * j + g) * FSTR + ks * 8 + tg;
                bf[0] = sK[kb]; bf[1] = sK[kb + 4];
                MMA_F16(s[j], aq, bf);
            }
        }

        const int kv = seqlen - k0;
        float mx0 = -1e30f, mx1 = -1e30f;
#pragma unroll
        for (int j = 0; j < 8; j++) {
            const int c0 = 8 * j + 2 * tg, c1 = c0 + 1;
            if (c0 >= kv) { s[j][0] = -1e30f; s[j][2] = -1e30f; }
            if (c1 >= kv) { s[j][1] = -1e30f; s[j][3] = -1e30f; }
            mx0 = fmaxf(mx0, fmaxf(s[j][0], s[j][1]));
            mx1 = fmaxf(mx1, fmaxf(s[j][2], s[j][3]));
        }
        mx0 = fmaxf(mx0, __shfl_xor_sync(0xffffffff, mx0, 1));
        mx0 = fmaxf(mx0, __shfl_xor_sync(0xffffffff, mx0, 2));
        mx1 = fmaxf(mx1, __shfl_xor_sync(0xffffffff, mx1, 1));
        mx1 = fmaxf(mx1, __shfl_xor_sync(0xffffffff, mx1, 2));
        const float mn0 = fmaxf(m[0], mx0);
        const float mn1 = fmaxf(m[1], mx1);
        const float a0 = __expf(m[0] - mn0);
        const float a1 = __expf(m[1] - mn1);
        m[0] = mn0; m[1] = mn1;

        float sum0 = 0.f, sum1 = 0.f;
#pragma unroll
        for (int j = 0; j < 8; j++) {
            s[j][0] = __expf(s[j][0] - mn0);
            s[j][1] = __expf(s[j][1] - mn0);
            s[j][2] = __expf(s[j][2] - mn1);
            s[j][3] = __expf(s[j][3] - mn1);
            sum0 += s[j][0] + s[j][1];
            sum1 += s[j][2] + s[j][3];
        }
        sum0 += __shfl_xor_sync(0xffffffff, sum0, 1);
        sum0 += __shfl_xor_sync(0xffffffff, sum0, 2);
        sum1 += __shfl_xor_sync(0xffffffff, sum1, 1);
        sum1 += __shfl_xor_sync(0xffffffff, sum1, 2);
        l[0] = l[0] * a0 + sum0;
        l[1] = l[1] * a1 + sum1;

#pragma unroll
        for (int n = 0; n < 16; n++) {
            o[n][0] *= a0; o[n][1] *= a0;
            o[n][2] *= a1; o[n][3] *= a1;
        }

#pragma unroll
        for (int kp = 0; kp < 4; kp++) {
            uint32_t ph[4];
            const int j0 = 2 * kp, j1 = 2 * kp + 1;
            ph[0] = pack2h(s[j0][0], s[j0][1]);
            ph[1] = pack2h(s[j0][2], s[j0][3]);
            ph[2] = pack2h(s[j1][0], s[j1][1]);
            ph[3] = pack2h(s[j1][2], s[j1][3]);
            const uint32_t vrow = bV + (uint32_t)(kp * 16 + (lane & 15)) * (FSTR * 4);
#pragma unroll
            for (int n2 = 0; n2 < 16; n2++) {
                uint32_t bv[2];
                asm volatile(
                    "ldmatrix.sync.aligned.m8n8.x2.trans.shared.b16 {%0,%1}, [%2];"
                    : "=r"(bv[0]), "=r"(bv[1])
                    : "r"(vrow + n2 * 16));
                MMA_F16(o[n2], ph, bv);
            }
        }
    }

    const float inv0 = 1.f / l[0];
    const float inv1 = 1.f / l[1];
    const int r0 = q0 + m0 + g;
    const int r1 = r0 + 8;
    uint32_t* oO = (uint32_t*)(O);
#pragma unroll
    for (int n = 0; n < 16; n++) {
        const int col = head * HDIM + 8 * n + 2 * tg;
        oO[(size_t)r0 * GROW + col / 2] = pack2h(o[n][0] * inv0, o[n][1] * inv0);
        oO[(size_t)r1 * GROW + col / 2] = pack2h(o[n][2] * inv1, o[n][3] * inv1);
    }
}

// ---------------------------------------------------------------------------
// Launch
// ---------------------------------------------------------------------------
extern "C" void kernel_launch(void* const* d_in, const int* in_sizes, int n_in,
                              void* d_out, int out_size) {
    const float* x         = (const float*)d_in[0];
    const int*   seq_lens  = (const int*)  d_in[1];
    const int*   grid_sz   = (const int*)  d_in[2];
    const float* freqs     = (const float*)d_in[3];
    const float* wq        = (const float*)d_in[4];
    const float* bq        = (const float*)d_in[5];
    const float* wk        = (const float*)d_in[6];
    const float* bk        = (const float*)d_in[7];
    const float* wv        = (const float*)d_in[8];
    const float* bv        = (const float*)d_in[9];
    const float* wo        = (const float*)d_in[10];
    const float* bo        = (const float*)d_in[11];
    const float* gq        = (const float*)d_in[12];
    const float* gk        = (const float*)d_in[13];
    float* out = (float*)d_out;

    float *q, *k, *dummy;
    cudaGetSymbolAddress((void**)&q, g_q);
    cudaGetSymbolAddress((void**)&k, g_k);
    cudaGetSymbolAddress((void**)&dummy, g_dummy);

    __half *xs, *as, *hwq, *hwk, *hwv, *hwo, *qs, *ks, *vs;
    cudaGetSymbolAddress((void**)&xs,  g_xs); cudaGetSymbolAddress((void**)&as,  g_as);
    cudaGetSymbolAddress((void**)&hwq, g_wq); cudaGetSymbolAddress((void**)&hwk, g_wk);
    cudaGetSymbolAddress((void**)&hwv, g_wv); cudaGetSymbolAddress((void**)&hwo, g_wo);
    cudaGetSymbolAddress((void**)&qs,  g_qs); cudaGetSymbolAddress((void**)&ks,  g_ks);
    cudaGetSymbolAddress((void**)&vs,  g_vs);

    const int gemm_smem = 2 * STG_BYTES;   // 40960 bytes
    cudaFuncSetAttribute(gemm_f16_pipe,
                         cudaFuncAttributeMaxDynamicSharedMemorySize, gemm_smem);

    // launch 1: all fp32->fp16 conversions (compile-time region dispatch)
    const int total4 = NX4 + 4 * NW4;
    conv_all<<<(total4 + 255) / 256, 256>>>(x, wq, wk, wv, wo,
                                            xs, hwq, hwk, hwv, hwo);

    // launch 2: fused QKV GEMM; V written directly as fp16
    GemmF16Batch qkv;
    qkv.B[0] = hwq; qkv.bias[0] = bq; qkv.C[0] = q;     qkv.Ch[0] = nullptr;
    qkv.B[1] = hwk; qkv.bias[1] = bk; qkv.C[1] = k;     qkv.Ch[1] = nullptr;
    qkv.B[2] = hwv; qkv.bias[2] = bv; qkv.C[2] = dummy; qkv.Ch[2] = vs;
    gemm_f16_pipe<<<dim3(DIM / 128, SEQ / 128, 3), 256, gemm_smem>>>(
        xs, qkv, SEQ, DIM, DIM);

    // launch 3: fused q+k norm/rope
    const float scale = 0.08838834764831845f;   // 1/sqrt(128)
    norm_rope_qk<<<dim3(SEQ, 2), 256>>>(q, k, gq, gk, qs, ks,
                                        freqs, grid_sz, scale);

    // launch 4: flash attention (R14 single-stage, occupancy 3)
    const size_t fl_smem = (size_t)(3 * 64 * FSTR) * sizeof(uint32_t);  // 52224
    cudaFuncSetAttribute(flash_f16s, cudaFuncAttributeMaxDynamicSharedMemorySize,
                         (int)fl_smem);
    flash_f16s<<<dim3(SEQ / 64, NHEADS), 128, fl_smem>>>(qs, ks, vs, seq_lens, as);

    // launch 5: O-projection GEMM
    GemmF16Batch ob;
    ob.B[0] = hwo; ob.bias[0] = bo; ob.C[0] = out; ob.Ch[0] = nullptr;
    ob.B[1] = hwo; ob.bias[1] = bo; ob.C[1] = out; ob.Ch[1] = nullptr;
    ob.B[2] = hwo; ob.bias[2] = bo; ob.C[2] = out; ob.Ch[2] = nullptr;
    gemm_f16_pipe<<<dim3(DIM / 128, SEQ / 128, 1), 256, gemm_smem>>>(
        as, ob, SEQ, DIM, DIM);
}